// round 1
// baseline (speedup 1.0000x reference)
#include <cuda_runtime.h>

#define HW    4096
#define NB    4
#define LOG2E 1.44269504088896340736f

// ---------------- scratch (device globals: allocation-free) ----------------
__device__ float g_Qc[NB * 64 * HW];   // [b][c][n], pre-scaled by log2e
__device__ float g_Kc[NB * 64 * HW];   // [b][c][n]
__device__ float g_Vw[NB * HW * 64];   // [b][n][c]  (w folded in)
__device__ float g_w [NB * HW];        // w[m] = 1 + beta*edge

// ---------------- f32x2 packed-FMA helpers (FFMA2) ----------------
__device__ __forceinline__ double dup2(float x) {
    double r; asm("mov.b64 %0, {%1,%1};" : "=d"(r) : "f"(x)); return r;
}
__device__ __forceinline__ void ffma2(double &d, double a, double b) {
    asm("fma.rn.f32x2 %0, %1, %2, %0;" : "+d"(d) : "d"(a), "d"(b));
}
__device__ __forceinline__ double fmul2(double a, double b) {
    double r; asm("mul.rn.f32x2 %0, %1, %2;" : "=d"(r) : "d"(a), "d"(b)); return r;
}
__device__ __forceinline__ void unpack2(double v, float &lo, float &hi) {
    asm("mov.b64 {%0,%1}, %2;" : "=f"(lo), "=f"(hi) : "d"(v));
}
__device__ __forceinline__ float ex2f(float x) {
    float r; asm("ex2.approx.f32 %0, %1;" : "=f"(r) : "f"(x)); return r;
}

// ================= kernel 1: edge detector -> g_w =================
// 3x3 conv (64->32) + folded BN + ReLU + 1x1 (32->1) + sigmoid
__global__ __launch_bounds__(128) void edge_kernel(
    const float* __restrict__ x,  const float* __restrict__ We1,
    const float* __restrict__ be1,
    const float* __restrict__ bn_w, const float* __restrict__ bn_b,
    const float* __restrict__ bn_mean, const float* __restrict__ bn_var,
    const float* __restrict__ We2, const float* __restrict__ be2,
    const float* __restrict__ beta)
{
    __shared__ __align__(16) float Wsh[32 * 9 * 32];   // [cc][k][ch] chunk
    __shared__ float s_sc[32], s_sh[32], s_w2[32];

    const int tid = threadIdx.x;
    const int b   = blockIdx.y;
    const int p   = blockIdx.x * 128 + tid;
    const int h   = p >> 6, w = p & 63;

    if (tid < 32) {
        float s = bn_w[tid] * rsqrtf(bn_var[tid] + 1e-5f);
        s_sc[tid] = s;
        s_sh[tid] = (be1[tid] - bn_mean[tid]) * s + bn_b[tid];
        s_w2[tid] = We2[tid];
    }

    double acc2[16];
    #pragma unroll
    for (int i = 0; i < 16; i++) acc2[i] = 0.0;

    for (int chunk = 0; chunk < 2; chunk++) {
        __syncthreads();
        for (int e = tid; e < 32 * 9 * 32; e += 128) {
            int ch = e & 31, rest = e >> 5;
            int k = rest % 9, cc = rest / 9;
            Wsh[e] = We1[((ch * 64) + (chunk * 32 + cc)) * 9 + k];
        }
        __syncthreads();
        const float* xb = x + (size_t)(b * 64 + chunk * 32) * HW;
        for (int cc = 0; cc < 32; cc++) {
            const float* xc = xb + cc * HW;
            #pragma unroll
            for (int k = 0; k < 9; k++) {
                const int dy = k / 3 - 1, dx = k % 3 - 1;
                const int hh = h + dy, ww = w + dx;
                float xv = 0.f;
                if (hh >= 0 && hh < 64 && ww >= 0 && ww < 64) xv = xc[hh * 64 + ww];
                double dv = dup2(xv);
                const double* wrow = (const double*)&Wsh[(cc * 9 + k) * 32];
                #pragma unroll
                for (int c2 = 0; c2 < 16; c2++) ffma2(acc2[c2], dv, wrow[c2]);
            }
        }
    }

    float e2 = be2[0];
    #pragma unroll
    for (int c2 = 0; c2 < 16; c2++) {
        float a, bb; unpack2(acc2[c2], a, bb);
        const int ch = c2 * 2;
        float r0 = fmaxf(a  * s_sc[ch]     + s_sh[ch],     0.f);
        float r1 = fmaxf(bb * s_sc[ch + 1] + s_sh[ch + 1], 0.f);
        e2 += s_w2[ch] * r0 + s_w2[ch + 1] * r1;
    }
    float sig = 1.f / (1.f + ex2f(-e2 * LOG2E));
    g_w[b * HW + p] = 1.f + beta[0] * sig;
}

// ================= kernel 2: QKV projections =================
// Q,K stored channel-major [b][c][n] (Q pre-scaled by log2e); Vw = (Wv x + bv)*w
// stored token-major [b][n][c].
__global__ __launch_bounds__(256) void qkv_kernel(
    const float* __restrict__ x,
    const float* __restrict__ Wq, const float* __restrict__ bq,
    const float* __restrict__ Wk, const float* __restrict__ bk,
    const float* __restrict__ Wv, const float* __restrict__ bv)
{
    __shared__ __align__(16) float xs[64 * 64];        // [c][n]
    __shared__ __align__(16) float WTq[32 * 64];       // [c_chunk][o]
    __shared__ __align__(16) float WTk[32 * 64];
    __shared__ __align__(16) float WTv[32 * 64];

    const int tid = threadIdx.x;
    const int b   = blockIdx.y;
    const int n0  = blockIdx.x * 64;

    for (int e = tid; e < 4096; e += 256) {
        int c = e >> 6, j = e & 63;
        xs[c * 64 + j] = x[(size_t)(b * 64 + c) * HW + n0 + j];
    }

    const int tn = tid & 15, to = tid >> 4;
    double aq[4][2], ak[4][2], av[4][2];
    #pragma unroll
    for (int i = 0; i < 4; i++) {
        aq[i][0] = aq[i][1] = 0.0; ak[i][0] = ak[i][1] = 0.0; av[i][0] = av[i][1] = 0.0;
    }

    for (int chunk = 0; chunk < 2; chunk++) {
        __syncthreads();
        for (int e = tid; e < 2048; e += 256) {
            int o = e & 63, c = e >> 6;
            WTq[c * 64 + o] = Wq[o * 64 + chunk * 32 + c];
            WTk[c * 64 + o] = Wk[o * 64 + chunk * 32 + c];
            WTv[c * 64 + o] = Wv[o * 64 + chunk * 32 + c];
        }
        __syncthreads();
        #pragma unroll 4
        for (int cc = 0; cc < 32; cc++) {
            const float4 xv = *(const float4*)&xs[(chunk * 32 + cc) * 64 + tn * 4];
            const double2 wq = *(const double2*)&WTq[cc * 64 + to * 4];
            const double2 wk = *(const double2*)&WTk[cc * 64 + to * 4];
            const double2 wv = *(const double2*)&WTv[cc * 64 + to * 4];
            double dn[4] = {dup2(xv.x), dup2(xv.y), dup2(xv.z), dup2(xv.w)};
            #pragma unroll
            for (int jn = 0; jn < 4; jn++) {
                ffma2(aq[jn][0], dn[jn], wq.x); ffma2(aq[jn][1], dn[jn], wq.y);
                ffma2(ak[jn][0], dn[jn], wk.x); ffma2(ak[jn][1], dn[jn], wk.y);
                ffma2(av[jn][0], dn[jn], wv.x); ffma2(av[jn][1], dn[jn], wv.y);
            }
        }
    }

    const int ob = to * 4;
    float bqv[4], bkv[4], bvv[4];
    #pragma unroll
    for (int io = 0; io < 4; io++) {
        bqv[io] = bq[ob + io]; bkv[io] = bk[ob + io]; bvv[io] = bv[ob + io];
    }
    #pragma unroll
    for (int jn = 0; jn < 4; jn++) {
        const int n = n0 + tn * 4 + jn;
        float q0,q1,q2,q3, k0,k1,k2,k3, v0,v1,v2,v3;
        unpack2(aq[jn][0], q0, q1); unpack2(aq[jn][1], q2, q3);
        unpack2(ak[jn][0], k0, k1); unpack2(ak[jn][1], k2, k3);
        unpack2(av[jn][0], v0, v1); unpack2(av[jn][1], v2, v3);
        const size_t base = ((size_t)(b * 64 + ob)) * HW + n;
        g_Qc[base           ] = (q0 + bqv[0]) * LOG2E;
        g_Qc[base +     HW  ] = (q1 + bqv[1]) * LOG2E;
        g_Qc[base + 2 * HW  ] = (q2 + bqv[2]) * LOG2E;
        g_Qc[base + 3 * HW  ] = (q3 + bqv[3]) * LOG2E;
        g_Kc[base           ] = k0 + bkv[0];
        g_Kc[base +     HW  ] = k1 + bkv[1];
        g_Kc[base + 2 * HW  ] = k2 + bkv[2];
        g_Kc[base + 3 * HW  ] = k3 + bkv[3];
        const float wnj = g_w[b * HW + n];
        float4 vo = make_float4((v0 + bvv[0]) * wnj, (v1 + bvv[1]) * wnj,
                                (v2 + bvv[2]) * wnj, (v3 + bvv[3]) * wnj);
        *(float4*)&g_Vw[((size_t)b * HW + n) * 64 + ob] = vo;
    }
}

// ================= kernel 3: flash attention (fused weight + L1 renorm) =====
// out[b,c,n] = gamma * (sum_m e^{s-m} w v) / (sum_m e^{s-m}|w|) + x[b,c,n]
__global__ __launch_bounds__(256, 1) void flash_kernel(
    const float* __restrict__ x, const float* __restrict__ gamma,
    float* __restrict__ out)
{
    extern __shared__ float sm[];
    float* QsT = sm;              // [64][128]
    float* KsT = sm + 8192;       // [64][128]
    float* Vs  = sm + 16384;      // [128][64]
    float* Ps  = sm + 24576;      // [128][128]
    float* aws = sm + 40960;      // [128]

    const int tid = threadIdx.x;
    const int b   = blockIdx.y;
    const int n0  = blockIdx.x * 128;
    const int tx  = tid & 15, ty = tid >> 4;

    const float* Qg = g_Qc + (size_t)b * 64 * HW;
    const float* Kg = g_Kc + (size_t)b * 64 * HW;
    const float* Vg = g_Vw + (size_t)b * HW * 64;

    for (int e = tid; e < 2048; e += 256) {
        int row = e >> 5, col = (e & 31) << 2;
        *(float4*)&QsT[row * 128 + col] =
            *(const float4*)(Qg + (size_t)row * HW + n0 + col);
    }

    double accO[8][2];
    float  mrow[8], drow[8];
    #pragma unroll
    for (int i = 0; i < 8; i++) { accO[i][0] = accO[i][1] = 0.0; mrow[i] = -1e30f; drow[i] = 0.f; }

    for (int t = 0; t < 32; t++) {
        const int m0 = t * 128;
        for (int e = tid; e < 2048; e += 256) {
            int row = e >> 5, col = (e & 31) << 2;
            *(float4*)&KsT[row * 128 + col] =
                *(const float4*)(Kg + (size_t)row * HW + m0 + col);
        }
        for (int e = tid; e < 2048; e += 256) {
            int row = e >> 4, col = (e & 15) << 2;
            *(float4*)&Vs[row * 64 + col] =
                *(const float4*)(Vg + (size_t)(m0 + row) * 64 + col);
        }
        if (tid < 128) aws[tid] = fabsf(g_w[b * HW + m0 + tid]);
        __syncthreads();

        // ---- S = (log2e*Q) K^T, 8x8 register tile on FFMA2 ----
        double accS[8][4];
        #pragma unroll
        for (int i = 0; i < 8; i++) { accS[i][0]=accS[i][1]=accS[i][2]=accS[i][3]=0.0; }
        #pragma unroll 8
        for (int c = 0; c < 64; c++) {
            const float4  qa  = *(const float4*) &QsT[c * 128 + ty * 8];
            const float4  qb  = *(const float4*) &QsT[c * 128 + ty * 8 + 4];
            const double2 k01 = *(const double2*)&KsT[c * 128 + tx * 8];
            const double2 k23 = *(const double2*)&KsT[c * 128 + tx * 8 + 4];
            const float qv[8] = {qa.x, qa.y, qa.z, qa.w, qb.x, qb.y, qb.z, qb.w};
            #pragma unroll
            for (int i = 0; i < 8; i++) {
                double dq = dup2(qv[i]);
                ffma2(accS[i][0], dq, k01.x);
                ffma2(accS[i][1], dq, k01.y);
                ffma2(accS[i][2], dq, k23.x);
                ffma2(accS[i][3], dq, k23.y);
            }
        }

        float awr[8];
        {
            const float4 a0 = *(const float4*)&aws[tx * 8];
            const float4 a1 = *(const float4*)&aws[tx * 8 + 4];
            awr[0]=a0.x; awr[1]=a0.y; awr[2]=a0.z; awr[3]=a0.w;
            awr[4]=a1.x; awr[5]=a1.y; awr[6]=a1.z; awr[7]=a1.w;
        }

        // ---- online softmax (state in registers, 16-lane shuffles) ----
        #pragma unroll
        for (int i = 0; i < 8; i++) {
            float s[8];
            unpack2(accS[i][0], s[0], s[1]);
            unpack2(accS[i][1], s[2], s[3]);
            unpack2(accS[i][2], s[4], s[5]);
            unpack2(accS[i][3], s[6], s[7]);
            float mx = s[0];
            #pragma unroll
            for (int j = 1; j < 8; j++) mx = fmaxf(mx, s[j]);
            #pragma unroll
            for (int off = 8; off >= 1; off >>= 1)
                mx = fmaxf(mx, __shfl_xor_sync(0xffffffffu, mx, off));
            const float mnew = fmaxf(mrow[i], mx);
            const float corr = ex2f(mrow[i] - mnew);
            mrow[i] = mnew;
            float p[8], rsum = 0.f;
            #pragma unroll
            for (int j = 0; j < 8; j++) { p[j] = ex2f(s[j] - mnew); rsum += p[j] * awr[j]; }
            #pragma unroll
            for (int off = 8; off >= 1; off >>= 1)
                rsum += __shfl_xor_sync(0xffffffffu, rsum, off);
            drow[i] = drow[i] * corr + rsum;
            const double dc = dup2(corr);
            accO[i][0] = fmul2(accO[i][0], dc);
            accO[i][1] = fmul2(accO[i][1], dc);
            float4 w0 = make_float4(p[0], p[1], p[2], p[3]);
            float4 w1 = make_float4(p[4], p[5], p[6], p[7]);
            *(float4*)&Ps[(ty * 8 + i) * 128 + tx * 8    ] = w0;
            *(float4*)&Ps[(ty * 8 + i) * 128 + tx * 8 + 4] = w1;
        }
        __syncthreads();

        // ---- O += P * Vw (8q x 4c tile on FFMA2) ----
        #pragma unroll 4
        for (int m = 0; m < 128; m++) {
            const double v0 = *(const double*)&Vs[m * 64 + tx * 4];
            const double v1 = *(const double*)&Vs[m * 64 + tx * 4 + 2];
            #pragma unroll
            for (int i = 0; i < 8; i++) {
                double dp = dup2(Ps[(ty * 8 + i) * 128 + m]);
                ffma2(accO[i][0], dp, v0);
                ffma2(accO[i][1], dp, v1);
            }
        }
        __syncthreads();
    }

    const float g0 = gamma[0];
    #pragma unroll
    for (int i = 0; i < 8; i++) {
        const float inv = 1.f / drow[i];
        float o0, o1, o2, o3;
        unpack2(accO[i][0], o0, o1);
        unpack2(accO[i][1], o2, o3);
        const int n  = n0 + ty * 8 + i;
        const int cb = tx * 4;
        const size_t base = ((size_t)(b * 64 + cb)) * HW + n;
        out[base         ] = g0 * o0 * inv + x[base         ];
        out[base +     HW] = g0 * o1 * inv + x[base +     HW];
        out[base + 2 * HW] = g0 * o2 * inv + x[base + 2 * HW];
        out[base + 3 * HW] = g0 * o3 * inv + x[base + 3 * HW];
    }
}

// ================= launch =================
extern "C" void kernel_launch(void* const* d_in, const int* in_sizes, int n_in,
                              void* d_out, int out_size)
{
    (void)in_sizes; (void)n_in; (void)out_size;
    const float* x       = (const float*)d_in[0];
    const float* Wq      = (const float*)d_in[1];
    const float* bq      = (const float*)d_in[2];
    const float* Wk      = (const float*)d_in[3];
    const float* bk      = (const float*)d_in[4];
    const float* Wv      = (const float*)d_in[5];
    const float* bv      = (const float*)d_in[6];
    const float* We1     = (const float*)d_in[7];
    const float* be1     = (const float*)d_in[8];
    const float* bn_w    = (const float*)d_in[9];
    const float* bn_b    = (const float*)d_in[10];
    const float* bn_mean = (const float*)d_in[11];
    const float* bn_var  = (const float*)d_in[12];
    const float* We2     = (const float*)d_in[13];
    const float* be2     = (const float*)d_in[14];
    const float* gamma   = (const float*)d_in[15];
    const float* beta    = (const float*)d_in[16];
    float* out = (float*)d_out;

    edge_kernel<<<dim3(32, NB), 128>>>(x, We1, be1, bn_w, bn_b, bn_mean, bn_var,
                                       We2, be2, beta);
    qkv_kernel<<<dim3(64, NB), 256>>>(x, Wq, bq, Wk, bk, Wv, bv);

    const int flash_smem = 41088 * 4;  // 164352 B
    cudaFuncSetAttribute(flash_kernel, cudaFuncAttributeMaxDynamicSharedMemorySize,
                         flash_smem);
    flash_kernel<<<dim3(32, NB), 256, flash_smem>>>(x, gamma, out);
}